// round 11
// baseline (speedup 1.0000x reference)
#include <cuda_runtime.h>
#include <cuda_bf16.h>
#include <stdint.h>

#define NB   32
#define MCH  16
#define HP   128
#define WPD  128
#define LTOT (126*126)      // 15876
#define OD   128
#define PD   144
#define CENTER 2.7416f      // E[chi_8]: analytic mean of pooled values

#define TILE_L 128
#define TILES_PER_N 125
#define NTILES (NB*TILES_PER_N)   // 4000
#define GRID_GEMM 296             // 2 CTAs/SM persistent

#define WS 152                    // smem row stride (halves); 304B = 19*16B -> conflict-free ldmatrix
#define W_BYTES (OD*WS*2)         // 38912
#define B_BYTES (TILE_L*WS*2)     // 38912
#define SMEM_BYTES (W_BYTES + B_BYTES)

// ---- static device scratch (no allocation) ----
__device__ __align__(32) __nv_bfloat16 g_pooled[NB*HP*WPD*MCH];  // channel-last, centered bf16
__device__ float g_const2[OD];   // b + CENTER * sum_k W
__device__ float g_acc[NB*OD];

// ---- helpers ----
__device__ __forceinline__ uint32_t smem_u32(const void* p) {
    uint32_t a;
    asm("{ .reg .u64 t; cvta.to.shared.u64 t, %1; cvt.u32.u64 %0, t; }" : "=r"(a) : "l"(p));
    return a;
}
__device__ __forceinline__ void ldsm_x4(uint32_t* r, uint32_t addr) {
    asm volatile("ldmatrix.sync.aligned.m8n8.x4.shared.b16 {%0,%1,%2,%3}, [%4];"
        : "=r"(r[0]), "=r"(r[1]), "=r"(r[2]), "=r"(r[3]) : "r"(addr));
}
__device__ __forceinline__ void mma16816(float* c, const uint32_t* a, uint32_t b0, uint32_t b1) {
    asm volatile(
        "mma.sync.aligned.m16n8k16.row.col.f32.bf16.bf16.f32 "
        "{%0,%1,%2,%3}, {%4,%5,%6,%7}, {%8,%9}, {%0,%1,%2,%3};\n"
        : "+f"(c[0]), "+f"(c[1]), "+f"(c[2]), "+f"(c[3])
        : "r"(a[0]), "r"(a[1]), "r"(a[2]), "r"(a[3]), "r"(b0), "r"(b1));
}

// ---- prep: fold bias + zero accumulators ----
__global__ void prep_kernel(const float* __restrict__ w, const float* __restrict__ b) {
    int tid = threadIdx.x;
    for (int i = tid; i < NB*OD; i += blockDim.x) g_acc[i] = 0.f;
    if (tid < OD) {
        float s = 0.f;
        #pragma unroll 4
        for (int k = 0; k < PD; k++) s += w[tid*PD + k];
        g_const2[tid] = b[tid] + CENTER * s;
    }
}

// ---- pass 1: LPPool3d + center + bf16, channel-last output via smem transpose ----
__global__ void pool_kernel(const float* __restrict__ x) {
    __shared__ __nv_bfloat16 s[128*18];   // [w][mc], stride 18 for bank spread
    int n = blockIdx.x >> 7;
    int h = blockIdx.x & 127;
    int t = threadIdx.x;
    int w = t & 127, mh = t >> 7;
    #pragma unroll
    for (int q = 0; q < 8; q++) {
        int mc = q*2 + mh;
        int dp = mc >> 3, c = mc & 7;
        const float* base = x + ((((n*8 + c)*4 + 2*dp) * 256 + 2*h) * 256 + 2*w);
        float sacc = 0.f;
        #pragma unroll
        for (int dd = 0; dd < 2; dd++)
            #pragma unroll
            for (int hh = 0; hh < 2; hh++) {
                float2 v = *(const float2*)(base + dd*65536 + hh*256);
                sacc += v.x*v.x + v.y*v.y;
            }
        s[w*18 + mc] = __float2bfloat16(sqrtf(sacc) - CENTER);
    }
    __syncthreads();
    int wo = t >> 1, g = (t & 1) * 8;
    uint4 out;
    out.x = *(const uint32_t*)&s[wo*18 + g + 0];
    out.y = *(const uint32_t*)&s[wo*18 + g + 2];
    out.z = *(const uint32_t*)&s[wo*18 + g + 4];
    out.w = *(const uint32_t*)&s[wo*18 + g + 6];
    *(uint4*)(g_pooled + ((n*HP + h)*WPD + wo)*MCH + g) = out;
}

// ---- pass 2: persistent mma.sync implicit-conv GEMM + CELU + sum ----
__global__ __launch_bounds__(256, 2) void gemm_kernel(const float* __restrict__ w) {
    extern __shared__ __align__(16) unsigned char smem[];
    __nv_bfloat16* sW = (__nv_bfloat16*)smem;
    unsigned char*  pB = smem + W_BYTES;
    uint32_t aW = smem_u32(smem);
    uint32_t aB = aW + W_BYTES;

    const int tid = threadIdx.x, warp = tid >> 5, lane = tid & 31;

    // stage W once: column k' = shift*16 + channel (matches B layout)
    for (int t = tid; t < OD*PD; t += 256) {
        int o = t / PD, kp = t - o*PD;
        int sft = kp >> 4, c = kp & 15;
        sW[o*WS + kp] = __float2bfloat16(w[o*PD + c*9 + sft]);
    }

    const int wm = warp & 3, wn = warp >> 2;   // 4 o-tiles x 2 l-halves
    const int g  = lane >> 2, th = lane & 3;
    const int obase = wm * 32;
    const int lbase = wn * 64;

    // per-thread constants (fixed across tiles)
    float cst[2][2];
    #pragma unroll
    for (int mt = 0; mt < 2; mt++) {
        cst[mt][0] = g_const2[obase + mt*16 + g];
        cst[mt][1] = g_const2[obase + mt*16 + g + 8];
    }

    // ldmatrix base addresses
    // A (W): x4 over 16 rows x 16 k: row = obase+mt*16+(lane&15), k-half = (lane>>4)*8
    uint32_t aA[2];
    #pragma unroll
    for (int mt = 0; mt < 2; mt++)
        aA[mt] = aW + (obase + mt*16 + (lane & 15)) * (WS*2) + (lane >> 4) * 16;
    // B: x4 over two 8-row n-tiles x 16 k: row = lbase+p*16+(lane&7)+((lane>>4)<<3),
    //    k-half = ((lane>>3)&1)*8
    uint32_t aBf[4];
    #pragma unroll
    for (int p = 0; p < 4; p++)
        aBf[p] = aB + (lbase + p*16 + (lane & 7) + ((lane >> 4) << 3)) * (WS*2)
                    + ((lane >> 3) & 1) * 16;

    __syncthreads();  // W staged

    for (int idx = blockIdx.x; idx < NTILES; idx += GRID_GEMM) {
        int n = idx / TILES_PER_N;
        int tile = idx - n*TILES_PER_N;
        int l0 = tile * TILE_L;

        // stage B once: sB[l][sft*16+c], 32B per (l,sft), fully vectorized
        for (int t = tid; t < 2304; t += 256) {
            int l = t / 18;
            int r = t - l*18;
            int sft = r >> 1, hf = r & 1;
            int lg = l0 + l; if (lg >= LTOT) lg = LTOT - 1;
            int pi = lg / 126, pj = lg - pi*126;
            int ki = sft / 3, kj = sft - 3*ki;
            const uint4* src = (const uint4*)(g_pooled +
                ((n*HP + pi + ki)*WPD + pj + kj)*MCH + hf*8);
            *(uint4*)(pB + l*(WS*2) + sft*32 + hf*16) = *src;
        }
        __syncthreads();

        float acc[2][8][4];
        #pragma unroll
        for (int mt = 0; mt < 2; mt++)
            #pragma unroll
            for (int nf = 0; nf < 8; nf++)
                #pragma unroll
                for (int q = 0; q < 4; q++) acc[mt][nf][q] = 0.f;

        #pragma unroll
        for (int s = 0; s < 9; s++) {
            uint32_t a0[4], a1[4];
            ldsm_x4(a0, aA[0] + s*32);
            ldsm_x4(a1, aA[1] + s*32);
            #pragma unroll
            for (int p = 0; p < 4; p++) {
                uint32_t bb[4];
                ldsm_x4(bb, aBf[p] + s*32);
                mma16816(acc[0][2*p],   a0, bb[0], bb[1]);
                mma16816(acc[0][2*p+1], a0, bb[2], bb[3]);
                mma16816(acc[1][2*p],   a1, bb[0], bb[1]);
                mma16816(acc[1][2*p+1], a1, bb[2], bb[3]);
            }
        }

        // epilogue: + const, CELU, masked sum over l, quad-reduce, atomicAdd
        #pragma unroll
        for (int mt = 0; mt < 2; mt++) {
            float s0 = 0.f, s1 = 0.f;
            #pragma unroll
            for (int nf = 0; nf < 8; nf++) {
                int lg = l0 + lbase + nf*8 + th*2;
                #pragma unroll
                for (int cc = 0; cc < 2; cc++) {
                    if (lg + cc < LTOT) {
                        float v = acc[mt][nf][cc] + cst[mt][0];
                        s0 += (v > 0.f) ? v : (__expf(v) - 1.f);
                        float u = acc[mt][nf][2 + cc] + cst[mt][1];
                        s1 += (u > 0.f) ? u : (__expf(u) - 1.f);
                    }
                }
            }
            #pragma unroll
            for (int off = 1; off < 4; off <<= 1) {
                s0 += __shfl_xor_sync(0xffffffffu, s0, off);
                s1 += __shfl_xor_sync(0xffffffffu, s1, off);
            }
            if (th == 0) {
                atomicAdd(&g_acc[n*OD + obase + mt*16 + g],     s0);
                atomicAdd(&g_acc[n*OD + obase + mt*16 + g + 8], s1);
            }
        }
        __syncthreads();  // all warps done reading sB before next staging
    }
}

// ---- pass 3: mean + clamped L2 normalize ----
__global__ void norm_kernel(float* __restrict__ out) {
    int n = blockIdx.x, o = threadIdx.x;
    float a = g_acc[n*OD + o] * (1.f / (float)LTOT);
    float ss = a * a;
    __shared__ float red[4];
    int lane = o & 31, w = o >> 5;
    #pragma unroll
    for (int off = 16; off; off >>= 1) ss += __shfl_xor_sync(0xffffffffu, ss, off);
    if (lane == 0) red[w] = ss;
    __syncthreads();
    float norm = sqrtf(red[0] + red[1] + red[2] + red[3]);
    out[n*OD + o] = a / fmaxf(norm, 1e-6f);
}

// ---- launch ----
extern "C" void kernel_launch(void* const* d_in, const int* in_sizes, int n_in,
                              void* d_out, int out_size) {
    const float* x = (const float*)d_in[0];
    const float* w = (const float*)d_in[1];
    const float* b = (const float*)d_in[2];
    float* out = (float*)d_out;

    prep_kernel<<<1, 256>>>(w, b);
    pool_kernel<<<NB*HP, 256>>>(x);
    cudaFuncSetAttribute(gemm_kernel, cudaFuncAttributeMaxDynamicSharedMemorySize, SMEM_BYTES);
    gemm_kernel<<<GRID_GEMM, 256, SMEM_BYTES>>>(w);
    norm_kernel<<<NB, 128>>>(out);
}

// round 12
// speedup vs baseline: 1.1246x; 1.1246x over previous
#include <cuda_runtime.h>
#include <cuda_bf16.h>
#include <stdint.h>

#define NB   32
#define MCH  16
#define HP   128
#define WPD  128
#define LTOT (126*126)      // 15876
#define OD   128
#define PD   144
#define CENTER 2.7416f      // E[chi_8]: analytic mean of pooled values

#define TILE_L 128
#define TILES_PER_N 125
#define NTILES (NB*TILES_PER_N)   // 4000
#define GRID_GEMM 148             // 1 CTA/SM persistent (A-in-registers needs 256 regs/thr)
#define PAD_PER_N 124             // 125*128 - 15876

#define WS 152                    // smem row stride (halves); 304B -> conflict-free ldmatrix
#define B_BYTES (TILE_L*WS*2)     // 38912
#define SMEM_BYTES (2*B_BYTES)    // double-buffered B (W lives in registers)

// ---- static device scratch (no allocation) ----
__device__ __align__(32) __nv_bfloat16 g_pooled[NB*HP*WPD*MCH];  // channel-last, centered bf16
__device__ __align__(16) __nv_bfloat16 g_zero[8];                // zero-init, pad source
__device__ float g_const2[OD];   // b + CENTER * sum_k W
__device__ float g_acc[NB*OD];

// ---- helpers ----
__device__ __forceinline__ uint32_t smem_u32(const void* p) {
    uint32_t a;
    asm("{ .reg .u64 t; cvta.to.shared.u64 t, %1; cvt.u32.u64 %0, t; }" : "=r"(a) : "l"(p));
    return a;
}
__device__ __forceinline__ void ldsm_x4(uint32_t* r, uint32_t addr) {
    asm volatile("ldmatrix.sync.aligned.m8n8.x4.shared.b16 {%0,%1,%2,%3}, [%4];"
        : "=r"(r[0]), "=r"(r[1]), "=r"(r[2]), "=r"(r[3]) : "r"(addr));
}
__device__ __forceinline__ void mma16816(float* c, const uint32_t* a, uint32_t b0, uint32_t b1) {
    asm volatile(
        "mma.sync.aligned.m16n8k16.row.col.f32.bf16.bf16.f32 "
        "{%0,%1,%2,%3}, {%4,%5,%6,%7}, {%8,%9}, {%0,%1,%2,%3};\n"
        : "+f"(c[0]), "+f"(c[1]), "+f"(c[2]), "+f"(c[3])
        : "r"(a[0]), "r"(a[1]), "r"(a[2]), "r"(a[3]), "r"(b0), "r"(b1));
}
__device__ __forceinline__ void cp16(uint32_t dst, const void* src) {
    asm volatile("cp.async.cg.shared.global [%0], [%1], 16;" :: "r"(dst), "l"(src) : "memory");
}

// ---- prep: fold bias + zero accumulators ----
__global__ void prep_kernel(const float* __restrict__ w, const float* __restrict__ b) {
    int tid = threadIdx.x;
    for (int i = tid; i < NB*OD; i += blockDim.x) g_acc[i] = 0.f;
    if (tid < OD) {
        float s = 0.f;
        #pragma unroll 4
        for (int k = 0; k < PD; k++) s += w[tid*PD + k];
        g_const2[tid] = b[tid] + CENTER * s;
    }
}

// ---- pass 1: LPPool3d + center + bf16, channel-last output via smem transpose ----
__global__ void pool_kernel(const float* __restrict__ x) {
    __shared__ __nv_bfloat16 s[128*18];   // [w][mc], stride 18 for bank spread
    int n = blockIdx.x >> 7;
    int h = blockIdx.x & 127;
    int t = threadIdx.x;
    int w = t & 127, mh = t >> 7;
    #pragma unroll
    for (int q = 0; q < 8; q++) {
        int mc = q*2 + mh;
        int dp = mc >> 3, c = mc & 7;
        const float* base = x + ((((n*8 + c)*4 + 2*dp) * 256 + 2*h) * 256 + 2*w);
        float sacc = 0.f;
        #pragma unroll
        for (int dd = 0; dd < 2; dd++)
            #pragma unroll
            for (int hh = 0; hh < 2; hh++) {
                float2 v = *(const float2*)(base + dd*65536 + hh*256);
                sacc += v.x*v.x + v.y*v.y;
            }
        s[w*18 + mc] = __float2bfloat16(sqrtf(sacc) - CENTER);
    }
    __syncthreads();
    int wo = t >> 1, g = (t & 1) * 8;
    uint4 out;
    out.x = *(const uint32_t*)&s[wo*18 + g + 0];
    out.y = *(const uint32_t*)&s[wo*18 + g + 2];
    out.z = *(const uint32_t*)&s[wo*18 + g + 4];
    out.w = *(const uint32_t*)&s[wo*18 + g + 6];
    *(uint4*)(g_pooled + ((n*HP + h)*WPD + wo)*MCH + g) = out;
}

// ---- pass 2: persistent mma.sync implicit-conv GEMM, A-in-regs, cp.async pipeline ----
__global__ __launch_bounds__(256, 1) void gemm_kernel(const float* __restrict__ w) {
    extern __shared__ __align__(16) unsigned char smem[];
    __nv_bfloat16* sB0h = (__nv_bfloat16*)smem;
    uint32_t aB0 = smem_u32(smem);

    const int tid = threadIdx.x, warp = tid >> 5, lane = tid & 31;
    const int wm = warp & 3, wn = warp >> 2;   // 4 o-tiles x 2 l-halves
    const int g  = lane >> 2, th = lane & 3;
    const int obase = wm * 32;
    const int lbase = wn * 64;

    // ---- stage W into buffer0, preload A fragments to registers ----
    for (int t = tid; t < OD*PD; t += 256) {
        int o = t / PD, kp = t - o*PD;
        int sft = kp >> 4, c = kp & 15;
        sB0h[o*WS + kp] = __float2bfloat16(w[o*PD + c*9 + sft]);
    }
    __syncthreads();
    uint32_t Afr[2][9][4];
    {
        uint32_t aA0 = aB0 + (obase + (lane & 15)) * (WS*2) + (lane >> 4) * 16;
        #pragma unroll
        for (int mt = 0; mt < 2; mt++)
            #pragma unroll
            for (int s = 0; s < 9; s++)
                ldsm_x4(Afr[mt][s], aA0 + mt*16*(WS*2) + s*32);
    }
    float cst[2][2];
    #pragma unroll
    for (int mt = 0; mt < 2; mt++) {
        cst[mt][0] = g_const2[obase + mt*16 + g];
        cst[mt][1] = g_const2[obase + mt*16 + g + 8];
    }
    __syncthreads();   // all A frags read before buffer0 is overwritten

    // B ldmatrix base (buffer-relative)
    uint32_t aBf[4];
    #pragma unroll
    for (int p = 0; p < 4; p++)
        aBf[p] = aB0 + (lbase + p*16 + (lane & 7) + ((lane >> 4) << 3)) * (WS*2)
                     + ((lane >> 3) & 1) * 16;

    // staging identity: thread -> (l, hf)
    const int sl = tid >> 1, shf = tid & 1;
    const uint32_t sdst0 = aB0 + sl*(WS*2) + shf*16;

    // ---- stage first tile ----
    int idx = blockIdx.x;
    {
        int n = idx / TILES_PER_N;
        int l0 = (idx - n*TILES_PER_N) * TILE_L;
        int lg = l0 + sl;
        bool valid = lg < LTOT;
        int pi = lg / 126, pj = lg - pi*126;
        const __nv_bfloat16* rb = g_pooled + ((n*HP + pi)*WPD + pj)*MCH + shf*8;
        #pragma unroll
        for (int sft = 0; sft < 9; sft++) {
            int ki = sft / 3, kj = sft - 3*ki;
            const void* src = valid ? (const void*)(rb + (ki*WPD + kj)*MCH) : (const void*)g_zero;
            cp16(sdst0 + sft*32, src);
        }
        asm volatile("cp.async.commit_group;" ::: "memory");
    }

    uint32_t boff = 0;
    for (; idx < NTILES; idx += GRID_GEMM) {
        asm volatile("cp.async.wait_group 0;" ::: "memory");
        __syncthreads();   // current buffer ready; all warps done with previous tile

        // stage next tile into other buffer (async, overlapped with compute)
        int nidx = idx + GRID_GEMM;
        if (nidx < NTILES) {
            int nn = nidx / TILES_PER_N;
            int nl0 = (nidx - nn*TILES_PER_N) * TILE_L;
            int lg = nl0 + sl;
            bool valid = lg < LTOT;
            int pi = lg / 126, pj = lg - pi*126;
            const __nv_bfloat16* rb = g_pooled + ((nn*HP + pi)*WPD + pj)*MCH + shf*8;
            uint32_t d = sdst0 + (boff ^ B_BYTES);
            #pragma unroll
            for (int sft = 0; sft < 9; sft++) {
                int ki = sft / 3, kj = sft - 3*ki;
                const void* src = valid ? (const void*)(rb + (ki*WPD + kj)*MCH) : (const void*)g_zero;
                cp16(d + sft*32, src);
            }
        }
        asm volatile("cp.async.commit_group;" ::: "memory");

        // ---- compute current tile ----
        float acc[2][8][4];
        #pragma unroll
        for (int mt = 0; mt < 2; mt++)
            #pragma unroll
            for (int nf = 0; nf < 8; nf++)
                #pragma unroll
                for (int q = 0; q < 4; q++) acc[mt][nf][q] = 0.f;

        #pragma unroll
        for (int s = 0; s < 9; s++) {
            #pragma unroll
            for (int p = 0; p < 4; p++) {
                uint32_t bb[4];
                ldsm_x4(bb, aBf[p] + boff + s*32);
                mma16816(acc[0][2*p],   Afr[0][s], bb[0], bb[1]);
                mma16816(acc[0][2*p+1], Afr[0][s], bb[2], bb[3]);
                mma16816(acc[1][2*p],   Afr[1][s], bb[0], bb[1]);
                mma16816(acc[1][2*p+1], Afr[1][s], bb[2], bb[3]);
            }
        }

        // epilogue: branch-free celu split max/exp (pad corrected in norm)
        int n = idx / TILES_PER_N;
        #pragma unroll
        for (int mt = 0; mt < 2; mt++) {
            float s0 = 0.f, s1 = 0.f, e0 = 0.f, e1 = 0.f;
            #pragma unroll
            for (int nf = 0; nf < 8; nf++) {
                #pragma unroll
                for (int cc = 0; cc < 2; cc++) {
                    float v = acc[mt][nf][cc] + cst[mt][0];
                    s0 += fmaxf(v, 0.f);
                    e0 += __expf(fminf(v, 0.f));
                    float u = acc[mt][nf][2 + cc] + cst[mt][1];
                    s1 += fmaxf(u, 0.f);
                    e1 += __expf(fminf(u, 0.f));
                }
            }
            s0 += e0; s1 += e1;
            #pragma unroll
            for (int off = 1; off < 4; off <<= 1) {
                s0 += __shfl_xor_sync(0xffffffffu, s0, off);
                s1 += __shfl_xor_sync(0xffffffffu, s1, off);
            }
            if (th == 0) {
                atomicAdd(&g_acc[n*OD + obase + mt*16 + g],     s0);
                atomicAdd(&g_acc[n*OD + obase + mt*16 + g + 8], s1);
            }
        }
        boff ^= B_BYTES;
    }
}

// ---- pass 3: pad-correct + mean + clamped L2 normalize ----
__global__ void norm_kernel(float* __restrict__ out) {
    int n = blockIdx.x, o = threadIdx.x;
    float cst = g_const2[o];
    float padv = fmaxf(cst, 0.f) + __expf(fminf(cst, 0.f));  // per padded patch (no -1)
    float a = (g_acc[n*OD + o] - (float)PAD_PER_N * padv - (float)LTOT) * (1.f / (float)LTOT);
    float ss = a * a;
    __shared__ float red[4];
    int lane = o & 31, w = o >> 5;
    #pragma unroll
    for (int off = 16; off; off >>= 1) ss += __shfl_xor_sync(0xffffffffu, ss, off);
    if (lane == 0) red[w] = ss;
    __syncthreads();
    float norm = sqrtf(red[0] + red[1] + red[2] + red[3]);
    out[n*OD + o] = a / fmaxf(norm, 1e-6f);
}

// ---- launch ----
extern "C" void kernel_launch(void* const* d_in, const int* in_sizes, int n_in,
                              void* d_out, int out_size) {
    const float* x = (const float*)d_in[0];
    const float* w = (const float*)d_in[1];
    const float* b = (const float*)d_in[2];
    float* out = (float*)d_out;

    prep_kernel<<<1, 256>>>(w, b);
    pool_kernel<<<NB*HP, 256>>>(x);
    cudaFuncSetAttribute(gemm_kernel, cudaFuncAttributeMaxDynamicSharedMemorySize, SMEM_BYTES);
    gemm_kernel<<<GRID_GEMM, 256, SMEM_BYTES>>>(w);
    norm_kernel<<<NB, 128>>>(out);
}

// round 13
// speedup vs baseline: 1.2856x; 1.1432x over previous
#include <cuda_runtime.h>
#include <cuda_bf16.h>
#include <stdint.h>

#define NB   32
#define MCH  16
#define HP   128
#define WPD  128
#define LTOT (126*126)      // 15876
#define OD   128
#define PD   144
#define CENTER 2.7416f      // E[chi_8]: analytic mean of pooled values

#define TILE_L 512
#define TILES_PER_N 32            // 32*512 = 16384 slots per n
#define NTILES (NB*TILES_PER_N)   // 1024
#define GRID_GEMM 148             // 1 CTA/SM persistent
#define PAD_PER_N 508             // 16384 - 15876

#define WS 152                    // W smem row stride (halves) for A-frag ldmatrix
#define WIN_ROWS 8
#define WIN_BYTES (WIN_ROWS*4096) // 32768: 8 rows x 128 w x 16 ch x 2B
#define SMEM_BYTES (2*WIN_BYTES + 16)

// ---- static device scratch (no allocation) ----
__device__ __align__(32) __nv_bfloat16 g_pooled[NB*HP*WPD*MCH];  // channel-last, centered bf16
__device__ float g_const2[OD];   // b + CENTER * sum_k W
__device__ float g_acc[NB*OD];

// ---- helpers ----
__device__ __forceinline__ uint32_t smem_u32(const void* p) {
    uint32_t a;
    asm("{ .reg .u64 t; cvta.to.shared.u64 t, %1; cvt.u32.u64 %0, t; }" : "=r"(a) : "l"(p));
    return a;
}
__device__ __forceinline__ void ldsm_x4(uint32_t* r, uint32_t addr) {
    asm volatile("ldmatrix.sync.aligned.m8n8.x4.shared.b16 {%0,%1,%2,%3}, [%4];"
        : "=r"(r[0]), "=r"(r[1]), "=r"(r[2]), "=r"(r[3]) : "r"(addr));
}
__device__ __forceinline__ void mma16816(float* c, const uint32_t* a, uint32_t b0, uint32_t b1) {
    asm volatile(
        "mma.sync.aligned.m16n8k16.row.col.f32.bf16.bf16.f32 "
        "{%0,%1,%2,%3}, {%4,%5,%6,%7}, {%8,%9}, {%0,%1,%2,%3};\n"
        : "+f"(c[0]), "+f"(c[1]), "+f"(c[2]), "+f"(c[3])
        : "r"(a[0]), "r"(a[1]), "r"(a[2]), "r"(a[3]), "r"(b0), "r"(b1));
}
__device__ __forceinline__ void cp16(uint32_t dst, const void* src) {
    asm volatile("cp.async.cg.shared.global [%0], [%1], 16;" :: "r"(dst), "l"(src) : "memory");
}

// ---- prep: fold bias + zero accumulators ----
__global__ void prep_kernel(const float* __restrict__ w, const float* __restrict__ b) {
    int tid = threadIdx.x;
    for (int i = tid; i < NB*OD; i += blockDim.x) g_acc[i] = 0.f;
    if (tid < OD) {
        float s = 0.f;
        #pragma unroll 4
        for (int k = 0; k < PD; k++) s += w[tid*PD + k];
        g_const2[tid] = b[tid] + CENTER * s;
    }
}

// ---- pass 1: LPPool3d + center + bf16, channel-last output via smem transpose ----
__global__ void pool_kernel(const float* __restrict__ x) {
    __shared__ __nv_bfloat16 s[128*18];   // [w][mc], stride 18 for bank spread
    int n = blockIdx.x >> 7;
    int h = blockIdx.x & 127;
    int t = threadIdx.x;
    int w = t & 127, mh = t >> 7;
    #pragma unroll
    for (int q = 0; q < 8; q++) {
        int mc = q*2 + mh;
        int dp = mc >> 3, c = mc & 7;
        const float* base = x + ((((n*8 + c)*4 + 2*dp) * 256 + 2*h) * 256 + 2*w);
        float sacc = 0.f;
        #pragma unroll
        for (int dd = 0; dd < 2; dd++)
            #pragma unroll
            for (int hh = 0; hh < 2; hh++) {
                float2 v = *(const float2*)(base + dd*65536 + hh*256);
                sacc += v.x*v.x + v.y*v.y;
            }
        s[w*18 + mc] = __float2bfloat16(sqrtf(sacc) - CENTER);
    }
    __syncthreads();
    int wo = t >> 1, g = (t & 1) * 8;
    uint4 out;
    out.x = *(const uint32_t*)&s[wo*18 + g + 0];
    out.y = *(const uint32_t*)&s[wo*18 + g + 2];
    out.z = *(const uint32_t*)&s[wo*18 + g + 4];
    out.w = *(const uint32_t*)&s[wo*18 + g + 6];
    *(uint4*)(g_pooled + ((n*HP + h)*WPD + wo)*MCH + g) = out;
}

// ---- pass 2: persistent mma.sync implicit-conv GEMM over 512-patch windows ----
// Window = unique merged data (8 rows x 128 w x 16 ch, channel-last), staged with
// 2048 coalesced 16B cp.asyncs; ldmatrix per-lane addressing does the 9-shift gather.
__global__ __launch_bounds__(256, 1) void gemm_kernel(const float* __restrict__ w) {
    extern __shared__ __align__(16) unsigned char smem[];
    uint32_t aS = smem_u32(smem);
    const uint32_t aZ = aS + 2*WIN_BYTES;   // 16B zero block

    const int tid = threadIdx.x, warp = tid >> 5, lane = tid & 31;
    const int wm = warp & 3, wn = warp >> 2;   // 4 o-tiles x 2 l-halves
    const int g  = lane >> 2, th = lane & 3;
    const int obase = wm * 32;
    const int lbase = wn * 64;
    const uint32_t hf16 = ((lane >> 3) & 1) * 16;
    const int rowoff = (lane & 7) + ((lane >> 4) << 3);

    // ---- stage W (temp, overlaps window region), preload A fragments ----
    {
        __nv_bfloat16* sW = (__nv_bfloat16*)smem;
        for (int t = tid; t < OD*PD; t += 256) {
            int o = t / PD, kp = t - o*PD;
            int sft = kp >> 4, c = kp & 15;
            sW[o*WS + kp] = __float2bfloat16(w[o*PD + c*9 + sft]);
        }
    }
    __syncthreads();
    uint32_t Afr[2][9][4];
    {
        uint32_t aA0 = aS + (obase + (lane & 15)) * (WS*2) + (lane >> 4) * 16;
        #pragma unroll
        for (int mt = 0; mt < 2; mt++)
            #pragma unroll
            for (int s = 0; s < 9; s++)
                ldsm_x4(Afr[mt][s], aA0 + mt*16*(WS*2) + s*32);
    }
    float cst[2][2];
    #pragma unroll
    for (int mt = 0; mt < 2; mt++) {
        cst[mt][0] = g_const2[obase + mt*16 + g];
        cst[mt][1] = g_const2[obase + mt*16 + g + 8];
    }
    if (tid == 0) *(uint4*)(smem + 2*WIN_BYTES) = make_uint4(0u, 0u, 0u, 0u);
    __syncthreads();   // A frags read + zero block ready; windows may now be written

    // staging: thread handles row k (0..7) at 16B chunk tid (XOR-16 swizzle)
    const uint32_t sdst_base = aS + ((uint32_t)(tid*16) ^ (uint32_t)((tid & 8) << 1));
    const __nv_bfloat16* srcb = g_pooled + tid*8;

    // ---- stage first window ----
    int idx = blockIdx.x;
    {
        int n = idx >> 5, tile = idx & 31;
        int pi0 = (tile << 9) / 126;
        #pragma unroll
        for (int r = 0; r < WIN_ROWS; r++) {
            int grow = pi0 + r; if (grow > 127) grow = 127;
            cp16(sdst_base + r*4096, srcb + (n*HP + grow)*WPD*MCH);
        }
        asm volatile("cp.async.commit_group;" ::: "memory");
    }

    uint32_t boff = 0;
    for (; idx < NTILES; idx += GRID_GEMM) {
        asm volatile("cp.async.wait_group 0;" ::: "memory");
        __syncthreads();   // current window ready; previous window's readers done

        int n = idx >> 5, tile = idx & 31;
        int l0 = tile << 9;
        int pi0 = l0 / 126;

        // stage next window into other buffer (overlapped with compute)
        int nidx = idx + GRID_GEMM;
        if (nidx < NTILES) {
            int nn = nidx >> 5, ntile = nidx & 31;
            int npi0 = (ntile << 9) / 126;
            uint32_t d = sdst_base + (boff ^ WIN_BYTES);
            #pragma unroll
            for (int r = 0; r < WIN_ROWS; r++) {
                int grow = npi0 + r; if (grow > 127) grow = 127;
                cp16(d + r*4096, srcb + (nn*HP + grow)*WPD*MCH);
            }
        }
        asm volatile("cp.async.commit_group;" ::: "memory");

        const uint32_t wbase = aS + boff;
        float rs[2][2] = {{0.f, 0.f}, {0.f, 0.f}};

        #pragma unroll
        for (int sub = 0; sub < 4; sub++) {
            // per-fragment lane row bases within the window
            uint32_t pb[4]; bool pv[4];
            #pragma unroll
            for (int p = 0; p < 4; p++) {
                int lg = l0 + sub*128 + lbase + p*16 + rowoff;
                unsigned pi = (unsigned)lg / 126u;
                unsigned pj = (unsigned)lg - pi*126u;
                pv[p] = lg < LTOT;
                pb[p] = (pi - (unsigned)pi0)*4096u + pj*32u + hf16;
            }

            float acc[2][8][4];
            #pragma unroll
            for (int mt = 0; mt < 2; mt++)
                #pragma unroll
                for (int nf = 0; nf < 8; nf++)
                    #pragma unroll
                    for (int q = 0; q < 4; q++) acc[mt][nf][q] = 0.f;

            #pragma unroll
            for (int s = 0; s < 9; s++) {
                const int ki = s / 3, kj = s - 3*ki;
                const uint32_t ko = ki*4096u + kj*32u;
                #pragma unroll
                for (int p = 0; p < 4; p++) {
                    uint32_t rel = pb[p] + ko;
                    rel ^= (rel >> 3) & 0x10u;      // bank de-conflict swizzle
                    uint32_t a = pv[p] ? (wbase + rel) : aZ;
                    uint32_t bb[4];
                    ldsm_x4(bb, a);
                    mma16816(acc[0][2*p],   Afr[0][s], bb[0], bb[1]);
                    mma16816(acc[0][2*p+1], Afr[0][s], bb[2], bb[3]);
                    mma16816(acc[1][2*p],   Afr[1][s], bb[0], bb[1]);
                    mma16816(acc[1][2*p+1], Afr[1][s], bb[2], bb[3]);
                }
            }

            // branch-free celu sums (pad corrected analytically in norm)
            #pragma unroll
            for (int mt = 0; mt < 2; mt++) {
                float s0 = 0.f, s1 = 0.f, e0 = 0.f, e1 = 0.f;
                #pragma unroll
                for (int nf = 0; nf < 8; nf++) {
                    #pragma unroll
                    for (int cc = 0; cc < 2; cc++) {
                        float v = acc[mt][nf][cc] + cst[mt][0];
                        s0 += fmaxf(v, 0.f);
                        e0 += __expf(fminf(v, 0.f));
                        float u = acc[mt][nf][2 + cc] + cst[mt][1];
                        s1 += fmaxf(u, 0.f);
                        e1 += __expf(fminf(u, 0.f));
                    }
                }
                rs[mt][0] += s0 + e0;
                rs[mt][1] += s1 + e1;
            }
        }

        #pragma unroll
        for (int mt = 0; mt < 2; mt++) {
            float s0 = rs[mt][0], s1 = rs[mt][1];
            #pragma unroll
            for (int off = 1; off < 4; off <<= 1) {
                s0 += __shfl_xor_sync(0xffffffffu, s0, off);
                s1 += __shfl_xor_sync(0xffffffffu, s1, off);
            }
            if (th == 0) {
                atomicAdd(&g_acc[n*OD + obase + mt*16 + g],     s0);
                atomicAdd(&g_acc[n*OD + obase + mt*16 + g + 8], s1);
            }
        }
        boff ^= WIN_BYTES;
    }
}

// ---- pass 3: pad-correct + mean + clamped L2 normalize ----
__global__ void norm_kernel(float* __restrict__ out) {
    int n = blockIdx.x, o = threadIdx.x;
    float cst = g_const2[o];
    float padv = fmaxf(cst, 0.f) + __expf(fminf(cst, 0.f));  // per padded slot (no -1)
    float a = (g_acc[n*OD + o] - (float)PAD_PER_N * padv - (float)LTOT) * (1.f / (float)LTOT);
    float ss = a * a;
    __shared__ float red[4];
    int lane = o & 31, w = o >> 5;
    #pragma unroll
    for (int off = 16; off; off >>= 1) ss += __shfl_xor_sync(0xffffffffu, ss, off);
    if (lane == 0) red[w] = ss;
    __syncthreads();
    float norm = sqrtf(red[0] + red[1] + red[2] + red[3]);
    out[n*OD + o] = a / fmaxf(norm, 1e-6f);
}

// ---- launch ----
extern "C" void kernel_launch(void* const* d_in, const int* in_sizes, int n_in,
                              void* d_out, int out_size) {
    const float* x = (const float*)d_in[0];
    const float* w = (const float*)d_in[1];
    const float* b = (const float*)d_in[2];
    float* out = (float*)d_out;

    prep_kernel<<<1, 256>>>(w, b);
    pool_kernel<<<NB*HP, 256>>>(x);
    cudaFuncSetAttribute(gemm_kernel, cudaFuncAttributeMaxDynamicSharedMemorySize, SMEM_BYTES);
    gemm_kernel<<<GRID_GEMM, 256, SMEM_BYTES>>>(w);
    norm_kernel<<<NB, 128>>>(out);
}